// round 14
// baseline (speedup 1.0000x reference)
#include <cuda_runtime.h>
#include <cuda_bf16.h>
#include <cstddef>

#define NN 100000
#define EE 1600000

// Scratch (device globals, referenced directly from device code)
__device__ int      g_degi[NN];
__device__ int      g_off[NN + 1];
__device__ int      g_cur[NN];
__device__ int      g_offL[NN];
__device__ int      g_part[128];
__device__ int      g_srcs[EE];              // dst-binned source indices
__device__ unsigned g_aggh[(size_t)NN * 64]; // mean(x) hi, packed (k,k+1) bf16x2
__device__ unsigned g_aggl[(size_t)NN * 64]; // mean(x) lo
__device__ unsigned g_hh[(size_t)NN * 64];   // h hi (bf16x2 pairs)
__device__ unsigned g_hl[(size_t)NN * 64];   // h lo
__device__ float    g_y[(size_t)NN * 64];    // h @ W2l (fp32)
// Pre-split weights, B-fragment packing: [n][k2] u32 = (W[2k2][n], W[2k2+1][n])
__device__ unsigned g_w1h[128 * 128], g_w1l[128 * 128];   // [W1l;W1r], K=256
__device__ unsigned g_w2h[128 * 64],  g_w2l[128 * 64];    // [W2l|W2r], K=128
__device__ int      g_is64;

// ---------------------------------------------------------------------------
// bf16 split + mma helpers
// ---------------------------------------------------------------------------
__device__ __forceinline__ void split2(float2 v, unsigned& hi, unsigned& lo) {
    __nv_bfloat162 h = __float22bfloat162_rn(v);
    float2 hf = __bfloat1622float2(h);
    __nv_bfloat162 l = __float22bfloat162_rn(make_float2(v.x - hf.x, v.y - hf.y));
    hi = *reinterpret_cast<unsigned*>(&h);
    lo = *reinterpret_cast<unsigned*>(&l);
}
__device__ __forceinline__ void mma_bf16(float4& d, const unsigned a[4],
                                         const unsigned b[2]) {
    asm volatile(
        "mma.sync.aligned.m16n8k16.row.col.f32.bf16.bf16.f32 "
        "{%0,%1,%2,%3}, {%4,%5,%6,%7}, {%8,%9}, {%0,%1,%2,%3};"
        : "+f"(d.x), "+f"(d.y), "+f"(d.z), "+f"(d.w)
        : "r"(a[0]), "r"(a[1]), "r"(a[2]), "r"(a[3]), "r"(b[0]), "r"(b[1]));
}

// load a clamped edge endpoint straight from the raw edge tensor
__device__ __forceinline__ int load_idx(const void* ei, int pos, int nE,
                                        int half, int n) {
    size_t idx = (size_t)half * nE + pos;
    long long v = g_is64 ? ((const long long*)ei)[idx]
                         : (long long)((const int*)ei)[idx];
    if (v < 0) v = 0;
    if (v >= n) v = n - 1;
    return (int)v;
}

// ---------------------------------------------------------------------------
// setup: dtype detect (thread 0) + zero degrees + pre-split weights
// ---------------------------------------------------------------------------
__global__ void setup_kernel(const int* __restrict__ ei32,
                             const float* __restrict__ W1lp,
                             const float* __restrict__ W1rp,
                             const float* __restrict__ W2lp,
                             const float* __restrict__ W2rp, int n) {
    int i = blockIdx.x * blockDim.x + threadIdx.x;
    if (i == 0) {
        int is64 = 1;
        for (int t = 0; t < 64; t++)
            if (ei32[2 * t + 1] != 0) { is64 = 0; break; }
        g_is64 = is64;
    }
    if (i < n) g_degi[i] = 0;
    if (i < 128 * 128) {                       // W1: [W1l;W1r], 128 n x 128 k2
        int nn = i >> 7, k2 = i & 127;
        int k = 2 * k2;
        float a, b;
        if (k < 128) { a = W1lp[k * 128 + nn]; b = W1lp[(k + 1) * 128 + nn]; }
        else         { a = W1rp[(k - 128) * 128 + nn]; b = W1rp[(k - 127) * 128 + nn]; }
        unsigned h, l; split2(make_float2(a, b), h, l);
        g_w1h[nn * 128 + k2] = h; g_w1l[nn * 128 + k2] = l;
    } else if (i < 128 * 128 + 128 * 64) {     // W2: [W2l|W2r], 128 n x 64 k2
        int j = i - 128 * 128;
        int nn = j >> 6, k2 = j & 63;
        int k = 2 * k2;
        float a, b;
        if (nn < 64) { a = W2lp[k * 64 + nn]; b = W2lp[(k + 1) * 64 + nn]; }
        else         { a = W2rp[k * 64 + nn - 64]; b = W2rp[(k + 1) * 64 + nn - 64]; }
        unsigned h, l; split2(make_float2(a, b), h, l);
        g_w2h[nn * 64 + k2] = h; g_w2l[nn * 64 + k2] = l;
    }
}

// ---------------------------------------------------------------------------
// degree count straight from raw edges
// ---------------------------------------------------------------------------
__global__ void count_kernel(const void* __restrict__ ei, int nE, int n) {
    int e = blockIdx.x * blockDim.x + threadIdx.x;
    if (e < nE) atomicAdd(&g_degi[load_idx(ei, e, nE, 1, n)], 1);
}

// ---------------------------------------------------------------------------
// 3-phase exclusive prefix scan of g_degi -> g_off (chunk = 1024)
// ---------------------------------------------------------------------------
__global__ void scan1_kernel(int n) {
    __shared__ int s[1024];
    const int tid = threadIdx.x;
    const int i = blockIdx.x * 1024 + tid;
    int v = (i < n) ? g_degi[i] : 0;
    s[tid] = v;
    __syncthreads();
#pragma unroll
    for (int d = 1; d < 1024; d <<= 1) {
        int t = (tid >= d) ? s[tid - d] : 0;
        __syncthreads();
        s[tid] += t;
        __syncthreads();
    }
    if (i < n) g_offL[i] = s[tid] - v;
    if (tid == 1023) g_part[blockIdx.x] = s[1023];
}
__global__ void scan2_kernel(int nb) {
    if (threadIdx.x == 0 && blockIdx.x == 0) {
        int acc = 0;
        for (int b = 0; b < nb; b++) { int t = g_part[b]; g_part[b] = acc; acc += t; }
    }
}
__global__ void scan3_kernel(int n, int nE) {
    int i = blockIdx.x * blockDim.x + threadIdx.x;
    if (i < n) {
        int off = g_offL[i] + g_part[i >> 10];
        g_off[i] = off;
        g_cur[i] = off;
    }
    if (i == 0) g_off[n] = nE;
}

// bin edges by dst straight from raw edges
__global__ void bin_kernel(const void* __restrict__ ei, int nE, int n) {
    int e = blockIdx.x * blockDim.x + threadIdx.x;
    if (e >= nE) return;
    int src = load_idx(ei, e, nE, 0, n);
    int dst = load_idx(ei, e, nE, 1, n);
    int pos = atomicAdd(&g_cur[dst], 1);
    g_srcs[pos] = src;
}

// ---------------------------------------------------------------------------
// Layer-1 aggregation: one warp per dst node; mean of x rows, written
// PRE-SPLIT (bf16 hi/lo, k-pair packed) for direct GEMM staging.
// ---------------------------------------------------------------------------
__global__ void gather1_kernel(const float* __restrict__ X, int n) {
    const int gw = (blockIdx.x * blockDim.x + threadIdx.x) >> 5;
    if (gw >= n) return;
    const int lane = threadIdx.x & 31;
    const int beg = g_off[gw], end = g_off[gw + 1];

    float4 acc = make_float4(0.f, 0.f, 0.f, 0.f);
    int j = beg;
    for (; j + 4 <= end; j += 4) {
        int s0 = g_srcs[j], s1 = g_srcs[j + 1];
        int s2 = g_srcs[j + 2], s3 = g_srcs[j + 3];
        float4 v0 = ((const float4*)(X + (size_t)s0 * 128))[lane];
        float4 v1 = ((const float4*)(X + (size_t)s1 * 128))[lane];
        float4 v2 = ((const float4*)(X + (size_t)s2 * 128))[lane];
        float4 v3 = ((const float4*)(X + (size_t)s3 * 128))[lane];
        acc.x += (v0.x + v1.x) + (v2.x + v3.x);
        acc.y += (v0.y + v1.y) + (v2.y + v3.y);
        acc.z += (v0.z + v1.z) + (v2.z + v3.z);
        acc.w += (v0.w + v1.w) + (v2.w + v3.w);
    }
    for (; j < end; j++) {
        float4 v = ((const float4*)(X + (size_t)g_srcs[j] * 128))[lane];
        acc.x += v.x; acc.y += v.y; acc.z += v.z; acc.w += v.w;
    }
    float r = 1.0f / (float)max(end - beg, 1);
    acc.x *= r; acc.y *= r; acc.z *= r; acc.w *= r;
    unsigned h0, l0, h1, l1;
    split2(make_float2(acc.x, acc.y), h0, l0);
    split2(make_float2(acc.z, acc.w), h1, l1);
    size_t base = (size_t)gw * 64 + 2 * lane;
    g_aggh[base] = h0; g_aggh[base + 1] = h1;
    g_aggl[base] = l0; g_aggl[base + 1] = l1;
}

// ---------------------------------------------------------------------------
// Layer-2 aggregation: mean of g_y rows, ACCUMULATED into out
// ---------------------------------------------------------------------------
__global__ void gather2_kernel(float* __restrict__ out, int n) {
    const int gw = (blockIdx.x * blockDim.x + threadIdx.x) >> 5;
    if (gw >= n) return;
    const int lane = threadIdx.x & 31;
    const int beg = g_off[gw], end = g_off[gw + 1];

    float2 acc = make_float2(0.f, 0.f);
    int j = beg;
    for (; j + 4 <= end; j += 4) {
        int s0 = g_srcs[j], s1 = g_srcs[j + 1];
        int s2 = g_srcs[j + 2], s3 = g_srcs[j + 3];
        float2 v0 = ((const float2*)(g_y + (size_t)s0 * 64))[lane];
        float2 v1 = ((const float2*)(g_y + (size_t)s1 * 64))[lane];
        float2 v2 = ((const float2*)(g_y + (size_t)s2 * 64))[lane];
        float2 v3 = ((const float2*)(g_y + (size_t)s3 * 64))[lane];
        acc.x += (v0.x + v1.x) + (v2.x + v3.x);
        acc.y += (v0.y + v1.y) + (v2.y + v3.y);
    }
    for (; j < end; j++) {
        float2 v = ((const float2*)(g_y + (size_t)g_srcs[j] * 64))[lane];
        acc.x += v.x; acc.y += v.y;
    }
    float r = 1.0f / (float)max(end - beg, 1);
    float2* p = (float2*)(out + (size_t)gw * 64) + lane;
    float2 o = *p;
    o.x += acc.x * r;
    o.y += acc.y * r;
    *p = o;
}

// ---------------------------------------------------------------------------
// GEMM 1: h = relu([mean(x) | x] @ [W1l;W1r] + b1), written pre-split bf16.
// BM=128, BN=128, K=256, KC=32, KHP=20. 8 warps: wm=warp&1 (2x64 M),
// wn=warp>>1 (4x32 N); warp tile 64x32 = 4 m16 x 4 n8.
// ---------------------------------------------------------------------------
__global__ void gemm1_kernel(const float* __restrict__ x,
                             const float* __restrict__ b1, int n) {
    constexpr int BM = 128, BN = 128, KHP = 20;
    __shared__ unsigned sAh[BM * KHP], sAl[BM * KHP];   // 10 KB each
    __shared__ unsigned sWh[BN * KHP], sWl[BN * KHP];   // 10 KB each
    const int tid = threadIdx.x;
    const int node0 = blockIdx.x * BM;
    const int warp = tid >> 5;
    const int lane = tid & 31;
    const int wm = warp & 1;
    const int wn = warp >> 1;
    const int gid = lane >> 2;
    const int tig = lane & 3;

    float4 acc[4][4];
#pragma unroll
    for (int mt = 0; mt < 4; mt++)
#pragma unroll
        for (int nt = 0; nt < 4; nt++)
            acc[mt][nt] = make_float4(0.f, 0.f, 0.f, 0.f);

    for (int kc = 0; kc < 256; kc += 32) {
        const int k2c = kc >> 1;               // 0,16,...,112
        if (kc < 128) {
            // A: copy pre-split agg columns [k2c, k2c+16)
            for (int t = tid; t < BM * 16; t += 256) {
                int m = t >> 4, k2 = t & 15;
                int node = node0 + m;
                unsigned h = 0, l = 0;
                if (node < n) {
                    h = g_aggh[(size_t)node * 64 + k2c + k2];
                    l = g_aggl[(size_t)node * 64 + k2c + k2];
                }
                sAh[m * KHP + k2] = h;
                sAl[m * KHP + k2] = l;
            }
        } else {
            // A: split x columns [kc-128, kc-96)
            const int koff = kc - 128;
            for (int t = tid; t < BM * 8; t += 256) {
                int m = t >> 3, kq = t & 7;
                int node = node0 + m;
                float4 v = make_float4(0.f, 0.f, 0.f, 0.f);
                if (node < n)
                    v = ((const float4*)(x + (size_t)node * 128 + koff))[kq];
                unsigned h0, l0, h1, l1;
                split2(make_float2(v.x, v.y), h0, l0);
                split2(make_float2(v.z, v.w), h1, l1);
                sAh[m * KHP + 2 * kq]     = h0;
                sAl[m * KHP + 2 * kq]     = l0;
                sAh[m * KHP + 2 * kq + 1] = h1;
                sAl[m * KHP + 2 * kq + 1] = l1;
            }
        }
        // W: copy pre-split columns
        for (int t = tid; t < BN * 16; t += 256) {
            int nn = t >> 4, k2 = t & 15;
            sWh[nn * KHP + k2] = g_w1h[nn * 128 + k2c + k2];
            sWl[nn * KHP + k2] = g_w1l[nn * 128 + k2c + k2];
        }
        __syncthreads();

#pragma unroll
        for (int k16 = 0; k16 < 2; k16++) {
            const int kh = k16 * 8;
            unsigned bh[4][2], bl[4][2];
#pragma unroll
            for (int nt = 0; nt < 4; nt++) {
                int rn = (wn * 32 + nt * 8 + gid) * KHP;
                bh[nt][0] = sWh[rn + kh + tig];
                bh[nt][1] = sWh[rn + kh + tig + 4];
                bl[nt][0] = sWl[rn + kh + tig];
                bl[nt][1] = sWl[rn + kh + tig + 4];
            }
#pragma unroll
            for (int mt = 0; mt < 4; mt++) {
                int r0 = (wm * 64 + mt * 16 + gid) * KHP;
                int r1 = r0 + 8 * KHP;
                unsigned ah[4], al[4];
                ah[0] = sAh[r0 + kh + tig];
                ah[1] = sAh[r1 + kh + tig];
                ah[2] = sAh[r0 + kh + tig + 4];
                ah[3] = sAh[r1 + kh + tig + 4];
                al[0] = sAl[r0 + kh + tig];
                al[1] = sAl[r1 + kh + tig];
                al[2] = sAl[r0 + kh + tig + 4];
                al[3] = sAl[r1 + kh + tig + 4];
#pragma unroll
                for (int nt = 0; nt < 4; nt++) {
                    mma_bf16(acc[mt][nt], ah, bh[nt]);
                    mma_bf16(acc[mt][nt], ah, bl[nt]);
                    mma_bf16(acc[mt][nt], al, bh[nt]);
                }
            }
        }
        __syncthreads();
    }

    // epilogue: bias + relu, write h PRE-SPLIT (pairs (c,c+1) = k-pair packing)
#pragma unroll
    for (int mt = 0; mt < 4; mt++) {
        int r0 = node0 + wm * 64 + mt * 16 + gid;
        int r1 = r0 + 8;
#pragma unroll
        for (int nt = 0; nt < 4; nt++) {
            int c = wn * 32 + nt * 8 + tig * 2;
            float bx = b1[c], by = b1[c + 1];
            if (r0 < n) {
                float2 v = make_float2(fmaxf(acc[mt][nt].x + bx, 0.f),
                                       fmaxf(acc[mt][nt].y + by, 0.f));
                unsigned h, l; split2(v, h, l);
                g_hh[(size_t)r0 * 64 + (c >> 1)] = h;
                g_hl[(size_t)r0 * 64 + (c >> 1)] = l;
            }
            if (r1 < n) {
                float2 v = make_float2(fmaxf(acc[mt][nt].z + bx, 0.f),
                                       fmaxf(acc[mt][nt].w + by, 0.f));
                unsigned h, l; split2(v, h, l);
                g_hh[(size_t)r1 * 64 + (c >> 1)] = h;
                g_hl[(size_t)r1 * 64 + (c >> 1)] = l;
            }
        }
    }
}

// ---------------------------------------------------------------------------
// GEMM 2 combined: [y | out_partial] = h @ [W2l | W2r]  (BM=128, BN=128, K=128)
// cols 0-63 -> g_y (fp32); cols 64-127 -> out = h@W2r + b2.
// ---------------------------------------------------------------------------
__global__ void gemm2c_kernel(const float* __restrict__ b2,
                              float* __restrict__ out, int n) {
    constexpr int BM = 128, BN = 128, KHP = 20;
    __shared__ unsigned sAh[BM * KHP], sAl[BM * KHP];
    __shared__ unsigned sWh[BN * KHP], sWl[BN * KHP];
    const int tid = threadIdx.x;
    const int node0 = blockIdx.x * BM;
    const int warp = tid >> 5;
    const int lane = tid & 31;
    const int wm = warp & 1;
    const int wn = warp >> 1;
    const int gid = lane >> 2;
    const int tig = lane & 3;

    float4 acc[4][4];
#pragma unroll
    for (int mt = 0; mt < 4; mt++)
#pragma unroll
        for (int nt = 0; nt < 4; nt++)
            acc[mt][nt] = make_float4(0.f, 0.f, 0.f, 0.f);

    for (int kc = 0; kc < 128; kc += 32) {
        const int k2c = kc >> 1;               // 0,16,32,48
        for (int t = tid; t < BM * 16; t += 256) {
            int m = t >> 4, k2 = t & 15;
            int node = node0 + m;
            unsigned h = 0, l = 0;
            if (node < n) {
                h = g_hh[(size_t)node * 64 + k2c + k2];
                l = g_hl[(size_t)node * 64 + k2c + k2];
            }
            sAh[m * KHP + k2] = h;
            sAl[m * KHP + k2] = l;
        }
        for (int t = tid; t < BN * 16; t += 256) {
            int nn = t >> 4, k2 = t & 15;
            sWh[nn * KHP + k2] = g_w2h[nn * 64 + k2c + k2];
            sWl[nn * KHP + k2] = g_w2l[nn * 64 + k2c + k2];
        }
        __syncthreads();

#pragma unroll
        for (int k16 = 0; k16 < 2; k16++) {
            const int kh = k16 * 8;
            unsigned bh[4][2], bl[4][2];
#pragma unroll
            for (int nt = 0; nt < 4; nt++) {
                int rn = (wn * 32 + nt * 8 + gid) * KHP;
                bh[nt][0] = sWh[rn + kh + tig];
                bh[nt][1] = sWh[rn + kh + tig + 4];
                bl[nt][0] = sWl[rn + kh + tig];
                bl[nt][1] = sWl[rn + kh + tig + 4];
            }
#pragma unroll
            for (int mt = 0; mt < 4; mt++) {
                int r0 = (wm * 64 + mt * 16 + gid) * KHP;
                int r1 = r0 + 8 * KHP;
                unsigned ah[4], al[4];
                ah[0] = sAh[r0 + kh + tig];
                ah[1] = sAh[r1 + kh + tig];
                ah[2] = sAh[r0 + kh + tig + 4];
                ah[3] = sAh[r1 + kh + tig + 4];
                al[0] = sAl[r0 + kh + tig];
                al[1] = sAl[r1 + kh + tig];
                al[2] = sAl[r0 + kh + tig + 4];
                al[3] = sAl[r1 + kh + tig + 4];
#pragma unroll
                for (int nt = 0; nt < 4; nt++) {
                    mma_bf16(acc[mt][nt], ah, bh[nt]);
                    mma_bf16(acc[mt][nt], ah, bl[nt]);
                    mma_bf16(acc[mt][nt], al, bh[nt]);
                }
            }
        }
        __syncthreads();
    }

    // epilogue: cols < 64 -> g_y; cols >= 64 -> out partial (+b2)
    const bool isY = (wn < 2);
#pragma unroll
    for (int mt = 0; mt < 4; mt++) {
        int r0 = node0 + wm * 64 + mt * 16 + gid;
#pragma unroll
        for (int nt = 0; nt < 4; nt++) {
            int c = wn * 32 + nt * 8 + tig * 2;
#pragma unroll
            for (int half = 0; half < 2; half++) {
                int r = r0 + half * 8;
                if (r >= n) continue;
                float vx = half ? acc[mt][nt].z : acc[mt][nt].x;
                float vy = half ? acc[mt][nt].w : acc[mt][nt].y;
                if (isY) {
                    *(float2*)(g_y + (size_t)r * 64 + c) = make_float2(vx, vy);
                } else {
                    int co = c - 64;
                    *(float2*)(out + (size_t)r * 64 + co) =
                        make_float2(vx + b2[co], vy + b2[co + 1]);
                }
            }
        }
    }
}

// ---------------------------------------------------------------------------
// launch
// ---------------------------------------------------------------------------
extern "C" void kernel_launch(void* const* d_in, const int* in_sizes, int n_in,
                              void* d_out, int out_size) {
    const float* x   = (const float*)d_in[0];
    const void*  ei  = d_in[1];
    const float* W1l = (const float*)d_in[2];
    const float* W1r = (const float*)d_in[3];
    const float* b1  = (const float*)d_in[4];
    const float* W2l = (const float*)d_in[5];
    const float* W2r = (const float*)d_in[6];
    const float* b2  = (const float*)d_in[7];
    float* out = (float*)d_out;

    const int n  = in_sizes[0] / 128;   // 100000
    const int nE = in_sizes[1] / 2;     // 1600000
    const int nb = (n + 1023) / 1024;

    setup_kernel<<<(n + 255) / 256, 256>>>((const int*)ei, W1l, W1r, W2l, W2r, n);
    count_kernel<<<(nE + 255) / 256, 256>>>(ei, nE, n);

    scan1_kernel<<<nb, 1024>>>(n);
    scan2_kernel<<<1, 32>>>(nb);
    scan3_kernel<<<(n + 255) / 256, 256>>>(n, nE);
    bin_kernel<<<(nE + 255) / 256, 256>>>(ei, nE, n);

    // ---- Layer 1 ----
    {
        long long threads = (long long)n * 32;
        gather1_kernel<<<(unsigned)((threads + 255) / 256), 256>>>(x, n);
    }
    gemm1_kernel<<<(n + 127) / 128, 256>>>(x, b1, n);

    // ---- Layer 2 ----
    gemm2c_kernel<<<(n + 127) / 128, 256>>>(b2, out, n);
    {
        long long threads = (long long)n * 32;
        gather2_kernel<<<(unsigned)((threads + 255) / 256), 256>>>(out, n);
    }
}

// round 15
// speedup vs baseline: 1.2059x; 1.2059x over previous
#include <cuda_runtime.h>
#include <cuda_bf16.h>
#include <cstddef>

#define NN 100000
#define EE 1600000

// Scratch (device globals, referenced directly from device code)
__device__ int      g_degi[NN];
__device__ int      g_off[NN + 1];
__device__ int      g_cur[NN];
__device__ int      g_offL[NN];
__device__ int      g_part[128];
__device__ int      g_srcs[EE];              // dst-binned source indices
__device__ unsigned g_aggh[(size_t)NN * 64]; // mean(x) hi, packed (k,k+1) bf16x2
__device__ unsigned g_aggl[(size_t)NN * 64]; // mean(x) lo
__device__ unsigned g_hh[(size_t)NN * 64];   // h hi (bf16x2 pairs)
__device__ unsigned g_hl[(size_t)NN * 64];   // h lo
__device__ float    g_y[(size_t)NN * 64];    // h @ W2l (fp32)
// Pre-split weights, B-fragment packing: [n][k2] u32 = (W[2k2][n], W[2k2+1][n])
__device__ unsigned g_w1h[128 * 128], g_w1l[128 * 128];   // [W1l;W1r], K=256
__device__ unsigned g_w2h[128 * 64],  g_w2l[128 * 64];    // [W2l|W2r], K=128
__device__ int      g_is64;

// ---------------------------------------------------------------------------
// bf16 split + mma helpers
// ---------------------------------------------------------------------------
__device__ __forceinline__ void split2(float2 v, unsigned& hi, unsigned& lo) {
    __nv_bfloat162 h = __float22bfloat162_rn(v);
    float2 hf = __bfloat1622float2(h);
    __nv_bfloat162 l = __float22bfloat162_rn(make_float2(v.x - hf.x, v.y - hf.y));
    hi = *reinterpret_cast<unsigned*>(&h);
    lo = *reinterpret_cast<unsigned*>(&l);
}
__device__ __forceinline__ void mma_bf16(float4& d, const unsigned a[4],
                                         const unsigned b[2]) {
    asm volatile(
        "mma.sync.aligned.m16n8k16.row.col.f32.bf16.bf16.f32 "
        "{%0,%1,%2,%3}, {%4,%5,%6,%7}, {%8,%9}, {%0,%1,%2,%3};"
        : "+f"(d.x), "+f"(d.y), "+f"(d.z), "+f"(d.w)
        : "r"(a[0]), "r"(a[1]), "r"(a[2]), "r"(a[3]), "r"(b[0]), "r"(b[1]));
}

// load a clamped edge endpoint straight from the raw edge tensor
__device__ __forceinline__ int load_idx(const void* ei, int pos, int nE,
                                        int half, int n) {
    size_t idx = (size_t)half * nE + pos;
    long long v = g_is64 ? ((const long long*)ei)[idx]
                         : (long long)((const int*)ei)[idx];
    if (v < 0) v = 0;
    if (v >= n) v = n - 1;
    return (int)v;
}

// ---------------------------------------------------------------------------
// setup: dtype detect (thread 0) + zero degrees + pre-split weights
// ---------------------------------------------------------------------------
__global__ void setup_kernel(const int* __restrict__ ei32,
                             const float* __restrict__ W1lp,
                             const float* __restrict__ W1rp,
                             const float* __restrict__ W2lp,
                             const float* __restrict__ W2rp, int n) {
    int i = blockIdx.x * blockDim.x + threadIdx.x;
    if (i == 0) {
        int is64 = 1;
        for (int t = 0; t < 64; t++)
            if (ei32[2 * t + 1] != 0) { is64 = 0; break; }
        g_is64 = is64;
    }
    if (i < n) g_degi[i] = 0;
    if (i < 128 * 128) {                       // W1: [W1l;W1r], 128 n x 128 k2
        int nn = i >> 7, k2 = i & 127;
        int k = 2 * k2;
        float a, b;
        if (k < 128) { a = W1lp[k * 128 + nn]; b = W1lp[(k + 1) * 128 + nn]; }
        else         { a = W1rp[(k - 128) * 128 + nn]; b = W1rp[(k - 127) * 128 + nn]; }
        unsigned h, l; split2(make_float2(a, b), h, l);
        g_w1h[nn * 128 + k2] = h; g_w1l[nn * 128 + k2] = l;
    } else if (i < 128 * 128 + 128 * 64) {     // W2: [W2l|W2r], 128 n x 64 k2
        int j = i - 128 * 128;
        int nn = j >> 6, k2 = j & 63;
        int k = 2 * k2;
        float a, b;
        if (nn < 64) { a = W2lp[k * 64 + nn]; b = W2lp[(k + 1) * 64 + nn]; }
        else         { a = W2rp[k * 64 + nn - 64]; b = W2rp[(k + 1) * 64 + nn - 64]; }
        unsigned h, l; split2(make_float2(a, b), h, l);
        g_w2h[nn * 64 + k2] = h; g_w2l[nn * 64 + k2] = l;
    }
}

// ---------------------------------------------------------------------------
// degree count straight from raw edges
// ---------------------------------------------------------------------------
__global__ void count_kernel(const void* __restrict__ ei, int nE, int n) {
    int e = blockIdx.x * blockDim.x + threadIdx.x;
    if (e < nE) atomicAdd(&g_degi[load_idx(ei, e, nE, 1, n)], 1);
}

// ---------------------------------------------------------------------------
// 3-phase exclusive prefix scan of g_degi -> g_off (chunk = 1024)
// ---------------------------------------------------------------------------
__global__ void scan1_kernel(int n) {
    __shared__ int s[1024];
    const int tid = threadIdx.x;
    const int i = blockIdx.x * 1024 + tid;
    int v = (i < n) ? g_degi[i] : 0;
    s[tid] = v;
    __syncthreads();
#pragma unroll
    for (int d = 1; d < 1024; d <<= 1) {
        int t = (tid >= d) ? s[tid - d] : 0;
        __syncthreads();
        s[tid] += t;
        __syncthreads();
    }
    if (i < n) g_offL[i] = s[tid] - v;
    if (tid == 1023) g_part[blockIdx.x] = s[1023];
}
__global__ void scan2_kernel(int nb) {
    if (threadIdx.x == 0 && blockIdx.x == 0) {
        int acc = 0;
        for (int b = 0; b < nb; b++) { int t = g_part[b]; g_part[b] = acc; acc += t; }
    }
}
__global__ void scan3_kernel(int n, int nE) {
    int i = blockIdx.x * blockDim.x + threadIdx.x;
    if (i < n) {
        int off = g_offL[i] + g_part[i >> 10];
        g_off[i] = off;
        g_cur[i] = off;
    }
    if (i == 0) g_off[n] = nE;
}

// bin edges by dst straight from raw edges
__global__ void bin_kernel(const void* __restrict__ ei, int nE, int n) {
    int e = blockIdx.x * blockDim.x + threadIdx.x;
    if (e >= nE) return;
    int src = load_idx(ei, e, nE, 0, n);
    int dst = load_idx(ei, e, nE, 1, n);
    int pos = atomicAdd(&g_cur[dst], 1);
    g_srcs[pos] = src;
}

// ---------------------------------------------------------------------------
// Layer-1 aggregation: one warp per dst node; mean of x rows, written
// PRE-SPLIT (bf16 hi/lo, k-pair packed) for direct GEMM staging.
// ---------------------------------------------------------------------------
__global__ void gather1_kernel(const float* __restrict__ X, int n) {
    const int gw = (blockIdx.x * blockDim.x + threadIdx.x) >> 5;
    if (gw >= n) return;
    const int lane = threadIdx.x & 31;
    const int beg = g_off[gw], end = g_off[gw + 1];

    float4 acc = make_float4(0.f, 0.f, 0.f, 0.f);
    int j = beg;
    for (; j + 4 <= end; j += 4) {
        int s0 = g_srcs[j], s1 = g_srcs[j + 1];
        int s2 = g_srcs[j + 2], s3 = g_srcs[j + 3];
        float4 v0 = ((const float4*)(X + (size_t)s0 * 128))[lane];
        float4 v1 = ((const float4*)(X + (size_t)s1 * 128))[lane];
        float4 v2 = ((const float4*)(X + (size_t)s2 * 128))[lane];
        float4 v3 = ((const float4*)(X + (size_t)s3 * 128))[lane];
        acc.x += (v0.x + v1.x) + (v2.x + v3.x);
        acc.y += (v0.y + v1.y) + (v2.y + v3.y);
        acc.z += (v0.z + v1.z) + (v2.z + v3.z);
        acc.w += (v0.w + v1.w) + (v2.w + v3.w);
    }
    for (; j < end; j++) {
        float4 v = ((const float4*)(X + (size_t)g_srcs[j] * 128))[lane];
        acc.x += v.x; acc.y += v.y; acc.z += v.z; acc.w += v.w;
    }
    float r = 1.0f / (float)max(end - beg, 1);
    acc.x *= r; acc.y *= r; acc.z *= r; acc.w *= r;
    unsigned h0, l0, h1, l1;
    split2(make_float2(acc.x, acc.y), h0, l0);
    split2(make_float2(acc.z, acc.w), h1, l1);
    size_t base = (size_t)gw * 64 + 2 * lane;
    g_aggh[base] = h0; g_aggh[base + 1] = h1;
    g_aggl[base] = l0; g_aggl[base + 1] = l1;
}

// ---------------------------------------------------------------------------
// Layer-2 aggregation: mean of g_y rows, ACCUMULATED into out
// ---------------------------------------------------------------------------
__global__ void gather2_kernel(float* __restrict__ out, int n) {
    const int gw = (blockIdx.x * blockDim.x + threadIdx.x) >> 5;
    if (gw >= n) return;
    const int lane = threadIdx.x & 31;
    const int beg = g_off[gw], end = g_off[gw + 1];

    float2 acc = make_float2(0.f, 0.f);
    int j = beg;
    for (; j + 4 <= end; j += 4) {
        int s0 = g_srcs[j], s1 = g_srcs[j + 1];
        int s2 = g_srcs[j + 2], s3 = g_srcs[j + 3];
        float2 v0 = ((const float2*)(g_y + (size_t)s0 * 64))[lane];
        float2 v1 = ((const float2*)(g_y + (size_t)s1 * 64))[lane];
        float2 v2 = ((const float2*)(g_y + (size_t)s2 * 64))[lane];
        float2 v3 = ((const float2*)(g_y + (size_t)s3 * 64))[lane];
        acc.x += (v0.x + v1.x) + (v2.x + v3.x);
        acc.y += (v0.y + v1.y) + (v2.y + v3.y);
    }
    for (; j < end; j++) {
        float2 v = ((const float2*)(g_y + (size_t)g_srcs[j] * 64))[lane];
        acc.x += v.x; acc.y += v.y;
    }
    float r = 1.0f / (float)max(end - beg, 1);
    float2* p = (float2*)(out + (size_t)gw * 64) + lane;
    float2 o = *p;
    o.x += acc.x * r;
    o.y += acc.y * r;
    *p = o;
}

// ---------------------------------------------------------------------------
// GEMM 1: h = relu([mean(x) | x] @ [W1l;W1r] + b1), written pre-split bf16.
// BM=64, BN=128, K=256, KC=32, KHP=20. 8 warps: wm=warp&1 (2x32 M),
// wn=warp>>1 (4x32 N); warp tile 32x32 = 2 m16 x 4 n8.  (R12 geometry)
// ---------------------------------------------------------------------------
__global__ void gemm1_kernel(const float* __restrict__ x,
                             const float* __restrict__ b1, int n) {
    constexpr int BM = 64, BN = 128, KHP = 20;
    __shared__ unsigned sAh[BM * KHP], sAl[BM * KHP];   // 5 KB each
    __shared__ unsigned sWh[BN * KHP], sWl[BN * KHP];   // 10 KB each
    const int tid = threadIdx.x;
    const int node0 = blockIdx.x * BM;
    const int warp = tid >> 5;
    const int lane = tid & 31;
    const int wm = warp & 1;
    const int wn = warp >> 1;
    const int gid = lane >> 2;
    const int tig = lane & 3;

    float4 acc[2][4];
#pragma unroll
    for (int mt = 0; mt < 2; mt++)
#pragma unroll
        for (int nt = 0; nt < 4; nt++)
            acc[mt][nt] = make_float4(0.f, 0.f, 0.f, 0.f);

    for (int kc = 0; kc < 256; kc += 32) {
        const int k2c = kc >> 1;               // 0,16,...,112
        if (kc < 128) {
            // A: copy pre-split agg columns [k2c, k2c+16)
            for (int t = tid; t < BM * 16; t += 256) {
                int m = t >> 4, k2 = t & 15;
                int node = node0 + m;
                unsigned h = 0, l = 0;
                if (node < n) {
                    h = g_aggh[(size_t)node * 64 + k2c + k2];
                    l = g_aggl[(size_t)node * 64 + k2c + k2];
                }
                sAh[m * KHP + k2] = h;
                sAl[m * KHP + k2] = l;
            }
        } else {
            // A: split x columns [kc-128, kc-96)
            const int koff = kc - 128;
            for (int t = tid; t < BM * 8; t += 256) {
                int m = t >> 3, kq = t & 7;
                int node = node0 + m;
                float4 v = make_float4(0.f, 0.f, 0.f, 0.f);
                if (node < n)
                    v = ((const float4*)(x + (size_t)node * 128 + koff))[kq];
                unsigned h0, l0, h1, l1;
                split2(make_float2(v.x, v.y), h0, l0);
                split2(make_float2(v.z, v.w), h1, l1);
                sAh[m * KHP + 2 * kq]     = h0;
                sAl[m * KHP + 2 * kq]     = l0;
                sAh[m * KHP + 2 * kq + 1] = h1;
                sAl[m * KHP + 2 * kq + 1] = l1;
            }
        }
        // W: copy pre-split columns
        for (int t = tid; t < BN * 16; t += 256) {
            int nn = t >> 4, k2 = t & 15;
            sWh[nn * KHP + k2] = g_w1h[nn * 128 + k2c + k2];
            sWl[nn * KHP + k2] = g_w1l[nn * 128 + k2c + k2];
        }
        __syncthreads();

#pragma unroll
        for (int k16 = 0; k16 < 2; k16++) {
            const int kh = k16 * 8;
            unsigned ah[2][4], al[2][4], bh[4][2], bl[4][2];
#pragma unroll
            for (int mt = 0; mt < 2; mt++) {
                int r0 = (wm * 32 + mt * 16 + gid) * KHP;
                int r1 = r0 + 8 * KHP;
                ah[mt][0] = sAh[r0 + kh + tig];
                ah[mt][1] = sAh[r1 + kh + tig];
                ah[mt][2] = sAh[r0 + kh + tig + 4];
                ah[mt][3] = sAh[r1 + kh + tig + 4];
                al[mt][0] = sAl[r0 + kh + tig];
                al[mt][1] = sAl[r1 + kh + tig];
                al[mt][2] = sAl[r0 + kh + tig + 4];
                al[mt][3] = sAl[r1 + kh + tig + 4];
            }
#pragma unroll
            for (int nt = 0; nt < 4; nt++) {
                int rn = (wn * 32 + nt * 8 + gid) * KHP;
                bh[nt][0] = sWh[rn + kh + tig];
                bh[nt][1] = sWh[rn + kh + tig + 4];
                bl[nt][0] = sWl[rn + kh + tig];
                bl[nt][1] = sWl[rn + kh + tig + 4];
            }
#pragma unroll
            for (int mt = 0; mt < 2; mt++)
#pragma unroll
                for (int nt = 0; nt < 4; nt++) {
                    mma_bf16(acc[mt][nt], ah[mt], bh[nt]);
                    mma_bf16(acc[mt][nt], ah[mt], bl[nt]);
                    mma_bf16(acc[mt][nt], al[mt], bh[nt]);
                }
        }
        __syncthreads();
    }

    // epilogue: bias + relu, write h PRE-SPLIT (pairs (c,c+1) = k-pair packing)
#pragma unroll
    for (int mt = 0; mt < 2; mt++) {
        int r0 = node0 + wm * 32 + mt * 16 + gid;
        int r1 = r0 + 8;
#pragma unroll
        for (int nt = 0; nt < 4; nt++) {
            int c = wn * 32 + nt * 8 + tig * 2;
            float bx = b1[c], by = b1[c + 1];
            if (r0 < n) {
                float2 v = make_float2(fmaxf(acc[mt][nt].x + bx, 0.f),
                                       fmaxf(acc[mt][nt].y + by, 0.f));
                unsigned h, l; split2(v, h, l);
                g_hh[(size_t)r0 * 64 + (c >> 1)] = h;
                g_hl[(size_t)r0 * 64 + (c >> 1)] = l;
            }
            if (r1 < n) {
                float2 v = make_float2(fmaxf(acc[mt][nt].z + bx, 0.f),
                                       fmaxf(acc[mt][nt].w + by, 0.f));
                unsigned h, l; split2(v, h, l);
                g_hh[(size_t)r1 * 64 + (c >> 1)] = h;
                g_hl[(size_t)r1 * 64 + (c >> 1)] = l;
            }
        }
    }
}

// ---------------------------------------------------------------------------
// GEMM 2 combined: [y | out_partial] = h @ [W2l | W2r]  (BM=64, BN=128, K=128)
// cols 0-63 -> g_y (fp32); cols 64-127 -> out = h@W2r + b2.  (R12 geometry)
// ---------------------------------------------------------------------------
__global__ void gemm2c_kernel(const float* __restrict__ b2,
                              float* __restrict__ out, int n) {
    constexpr int BM = 64, BN = 128, KHP = 20;
    __shared__ unsigned sAh[BM * KHP], sAl[BM * KHP];
    __shared__ unsigned sWh[BN * KHP], sWl[BN * KHP];
    const int tid = threadIdx.x;
    const int node0 = blockIdx.x * BM;
    const int warp = tid >> 5;
    const int lane = tid & 31;
    const int wm = warp & 1;
    const int wn = warp >> 1;
    const int gid = lane >> 2;
    const int tig = lane & 3;

    float4 acc[2][4];
#pragma unroll
    for (int mt = 0; mt < 2; mt++)
#pragma unroll
        for (int nt = 0; nt < 4; nt++)
            acc[mt][nt] = make_float4(0.f, 0.f, 0.f, 0.f);

    for (int kc = 0; kc < 128; kc += 32) {
        const int k2c = kc >> 1;               // 0,16,32,48
        for (int t = tid; t < BM * 16; t += 256) {
            int m = t >> 4, k2 = t & 15;
            int node = node0 + m;
            unsigned h = 0, l = 0;
            if (node < n) {
                h = g_hh[(size_t)node * 64 + k2c + k2];
                l = g_hl[(size_t)node * 64 + k2c + k2];
            }
            sAh[m * KHP + k2] = h;
            sAl[m * KHP + k2] = l;
        }
        for (int t = tid; t < BN * 16; t += 256) {
            int nn = t >> 4, k2 = t & 15;
            sWh[nn * KHP + k2] = g_w2h[nn * 64 + k2c + k2];
            sWl[nn * KHP + k2] = g_w2l[nn * 64 + k2c + k2];
        }
        __syncthreads();

#pragma unroll
        for (int k16 = 0; k16 < 2; k16++) {
            const int kh = k16 * 8;
            unsigned ah[2][4], al[2][4], bh[4][2], bl[4][2];
#pragma unroll
            for (int mt = 0; mt < 2; mt++) {
                int r0 = (wm * 32 + mt * 16 + gid) * KHP;
                int r1 = r0 + 8 * KHP;
                ah[mt][0] = sAh[r0 + kh + tig];
                ah[mt][1] = sAh[r1 + kh + tig];
                ah[mt][2] = sAh[r0 + kh + tig + 4];
                ah[mt][3] = sAh[r1 + kh + tig + 4];
                al[mt][0] = sAl[r0 + kh + tig];
                al[mt][1] = sAl[r1 + kh + tig];
                al[mt][2] = sAl[r0 + kh + tig + 4];
                al[mt][3] = sAl[r1 + kh + tig + 4];
            }
#pragma unroll
            for (int nt = 0; nt < 4; nt++) {
                int rn = (wn * 32 + nt * 8 + gid) * KHP;
                bh[nt][0] = sWh[rn + kh + tig];
                bh[nt][1] = sWh[rn + kh + tig + 4];
                bl[nt][0] = sWl[rn + kh + tig];
                bl[nt][1] = sWl[rn + kh + tig + 4];
            }
#pragma unroll
            for (int mt = 0; mt < 2; mt++)
#pragma unroll
                for (int nt = 0; nt < 4; nt++) {
                    mma_bf16(acc[mt][nt], ah[mt], bh[nt]);
                    mma_bf16(acc[mt][nt], ah[mt], bl[nt]);
                    mma_bf16(acc[mt][nt], al[mt], bh[nt]);
                }
        }
        __syncthreads();
    }

    // epilogue: cols < 64 -> g_y; cols >= 64 -> out partial (+b2)
    const bool isY = (wn < 2);
#pragma unroll
    for (int mt = 0; mt < 2; mt++) {
        int r0 = node0 + wm * 32 + mt * 16 + gid;
#pragma unroll
        for (int nt = 0; nt < 4; nt++) {
            int c = wn * 32 + nt * 8 + tig * 2;
#pragma unroll
            for (int half = 0; half < 2; half++) {
                int r = r0 + half * 8;
                if (r >= n) continue;
                float vx = half ? acc[mt][nt].z : acc[mt][nt].x;
                float vy = half ? acc[mt][nt].w : acc[mt][nt].y;
                if (isY) {
                    *(float2*)(g_y + (size_t)r * 64 + c) = make_float2(vx, vy);
                } else {
                    int co = c - 64;
                    *(float2*)(out + (size_t)r * 64 + co) =
                        make_float2(vx + b2[co], vy + b2[co + 1]);
                }
            }
        }
    }
}

// ---------------------------------------------------------------------------
// launch
// ---------------------------------------------------------------------------
extern "C" void kernel_launch(void* const* d_in, const int* in_sizes, int n_in,
                              void* d_out, int out_size) {
    const float* x   = (const float*)d_in[0];
    const void*  ei  = d_in[1];
    const float* W1l = (const float*)d_in[2];
    const float* W1r = (const float*)d_in[3];
    const float* b1  = (const float*)d_in[4];
    const float* W2l = (const float*)d_in[5];
    const float* W2r = (const float*)d_in[6];
    const float* b2  = (const float*)d_in[7];
    float* out = (float*)d_out;

    const int n  = in_sizes[0] / 128;   // 100000
    const int nE = in_sizes[1] / 2;     // 1600000
    const int nb = (n + 1023) / 1024;

    setup_kernel<<<(n + 255) / 256, 256>>>((const int*)ei, W1l, W1r, W2l, W2r, n);
    count_kernel<<<(nE + 255) / 256, 256>>>(ei, nE, n);

    scan1_kernel<<<nb, 1024>>>(n);
    scan2_kernel<<<1, 32>>>(nb);
    scan3_kernel<<<(n + 255) / 256, 256>>>(n, nE);
    bin_kernel<<<(nE + 255) / 256, 256>>>(ei, nE, n);

    // ---- Layer 1 ----
    {
        long long threads = (long long)n * 32;
        gather1_kernel<<<(unsigned)((threads + 255) / 256), 256>>>(x, n);
    }
    gemm1_kernel<<<(n + 63) / 64, 256>>>(x, b1, n);

    // ---- Layer 2 ----
    gemm2c_kernel<<<(n + 63) / 64, 256>>>(b2, out, n);
    {
        long long threads = (long long)n * 32;
        gather2_kernel<<<(unsigned)((threads + 255) / 256), 256>>>(out, n);
    }
}

// round 17
// speedup vs baseline: 1.4052x; 1.1653x over previous
#include <cuda_runtime.h>
#include <cuda_bf16.h>
#include <cstddef>

#define NN 100000
#define EE 1600000

// Scratch (device globals, referenced directly from device code)
__device__ int      g_degi[NN];
__device__ int      g_off[NN + 1];
__device__ int      g_cur[NN];
__device__ int      g_offL[NN];
__device__ int      g_part[128];
__device__ int      g_srcs[EE];              // dst-binned source indices
__device__ unsigned g_aggh[(size_t)NN * 64]; // mean(x) hi, packed (k,k+1) bf16x2
__device__ unsigned g_aggl[(size_t)NN * 64]; // mean(x) lo
__device__ unsigned g_hh[(size_t)NN * 64];   // h hi (bf16x2 pairs)
__device__ unsigned g_hl[(size_t)NN * 64];   // h lo
__device__ float    g_y[(size_t)NN * 64];    // h @ W2l (fp32)
// Pre-split weights, B-fragment packing: [n][k2] u32 = (W[2k2][n], W[2k2+1][n])
__device__ unsigned g_w1h[128 * 128], g_w1l[128 * 128];   // [W1l;W1r], K=256
__device__ unsigned g_w2h[128 * 64],  g_w2l[128 * 64];    // [W2l|W2r], K=128
__device__ int      g_is64;

// ---------------------------------------------------------------------------
// helpers
// ---------------------------------------------------------------------------
__device__ __forceinline__ void split2(float2 v, unsigned& hi, unsigned& lo) {
    __nv_bfloat162 h = __float22bfloat162_rn(v);
    float2 hf = __bfloat1622float2(h);
    __nv_bfloat162 l = __float22bfloat162_rn(make_float2(v.x - hf.x, v.y - hf.y));
    hi = *reinterpret_cast<unsigned*>(&h);
    lo = *reinterpret_cast<unsigned*>(&l);
}
__device__ __forceinline__ void mma_bf16(float4& d, const unsigned a[4],
                                         const unsigned b[2]) {
    asm volatile(
        "mma.sync.aligned.m16n8k16.row.col.f32.bf16.bf16.f32 "
        "{%0,%1,%2,%3}, {%4,%5,%6,%7}, {%8,%9}, {%0,%1,%2,%3};"
        : "+f"(d.x), "+f"(d.y), "+f"(d.z), "+f"(d.w)
        : "r"(a[0]), "r"(a[1]), "r"(a[2]), "r"(a[3]), "r"(b[0]), "r"(b[1]));
}
__device__ __forceinline__ unsigned smem_u32p(const void* p) {
    return (unsigned)__cvta_generic_to_shared(p);
}
#define CPA16(dst, src, sz) \
    asm volatile("cp.async.cg.shared.global [%0], [%1], 16, %2;" \
                 :: "r"(dst), "l"(src), "r"(sz) : "memory")
#define CPA_COMMIT() asm volatile("cp.async.commit_group;" ::: "memory")
#define CPA_WAIT0()  asm volatile("cp.async.wait_group 0;" ::: "memory")

// load a clamped edge endpoint straight from the raw edge tensor
__device__ __forceinline__ int load_idx(const void* ei, int pos, int nE,
                                        int half, int n) {
    size_t idx = (size_t)half * nE + pos;
    long long v = g_is64 ? ((const long long*)ei)[idx]
                         : (long long)((const int*)ei)[idx];
    if (v < 0) v = 0;
    if (v >= n) v = n - 1;
    return (int)v;
}

// ---------------------------------------------------------------------------
// setup: dtype detect (thread 0) + zero degrees + pre-split weights
// ---------------------------------------------------------------------------
__global__ void setup_kernel(const int* __restrict__ ei32,
                             const float* __restrict__ W1lp,
                             const float* __restrict__ W1rp,
                             const float* __restrict__ W2lp,
                             const float* __restrict__ W2rp, int n) {
    int i = blockIdx.x * blockDim.x + threadIdx.x;
    if (i == 0) {
        int is64 = 1;
        for (int t = 0; t < 64; t++)
            if (ei32[2 * t + 1] != 0) { is64 = 0; break; }
        g_is64 = is64;
    }
    if (i < n) g_degi[i] = 0;
    if (i < 128 * 128) {                       // W1: [W1l;W1r], 128 n x 128 k2
        int nn = i >> 7, k2 = i & 127;
        int k = 2 * k2;
        float a, b;
        if (k < 128) { a = W1lp[k * 128 + nn]; b = W1lp[(k + 1) * 128 + nn]; }
        else         { a = W1rp[(k - 128) * 128 + nn]; b = W1rp[(k - 127) * 128 + nn]; }
        unsigned h, l; split2(make_float2(a, b), h, l);
        g_w1h[nn * 128 + k2] = h; g_w1l[nn * 128 + k2] = l;
    } else if (i < 128 * 128 + 128 * 64) {     // W2: [W2l|W2r], 128 n x 64 k2
        int j = i - 128 * 128;
        int nn = j >> 6, k2 = j & 63;
        int k = 2 * k2;
        float a, b;
        if (nn < 64) { a = W2lp[k * 64 + nn]; b = W2lp[(k + 1) * 64 + nn]; }
        else         { a = W2rp[k * 64 + nn - 64]; b = W2rp[(k + 1) * 64 + nn - 64]; }
        unsigned h, l; split2(make_float2(a, b), h, l);
        g_w2h[nn * 64 + k2] = h; g_w2l[nn * 64 + k2] = l;
    }
}

// ---------------------------------------------------------------------------
// degree count straight from raw edges
// ---------------------------------------------------------------------------
__global__ void count_kernel(const void* __restrict__ ei, int nE, int n) {
    int e = blockIdx.x * blockDim.x + threadIdx.x;
    if (e < nE) atomicAdd(&g_degi[load_idx(ei, e, nE, 1, n)], 1);
}

// ---------------------------------------------------------------------------
// 3-phase exclusive prefix scan of g_degi -> g_off (chunk = 1024)
// ---------------------------------------------------------------------------
__global__ void scan1_kernel(int n) {
    __shared__ int s[1024];
    const int tid = threadIdx.x;
    const int i = blockIdx.x * 1024 + tid;
    int v = (i < n) ? g_degi[i] : 0;
    s[tid] = v;
    __syncthreads();
#pragma unroll
    for (int d = 1; d < 1024; d <<= 1) {
        int t = (tid >= d) ? s[tid - d] : 0;
        __syncthreads();
        s[tid] += t;
        __syncthreads();
    }
    if (i < n) g_offL[i] = s[tid] - v;
    if (tid == 1023) g_part[blockIdx.x] = s[1023];
}
// parallel exclusive scan of block partials (nb <= 128)
__global__ void scan2_kernel(int nb) {
    __shared__ int s[128];
    int t = threadIdx.x;
    int v = (t < nb) ? g_part[t] : 0;
    s[t] = v;
    __syncthreads();
#pragma unroll
    for (int d = 1; d < 128; d <<= 1) {
        int u = (t >= d) ? s[t - d] : 0;
        __syncthreads();
        s[t] += u;
        __syncthreads();
    }
    if (t < nb) g_part[t] = s[t] - v;
}
__global__ void scan3_kernel(int n, int nE) {
    int i = blockIdx.x * blockDim.x + threadIdx.x;
    if (i < n) {
        int off = g_offL[i] + g_part[i >> 10];
        g_off[i] = off;
        g_cur[i] = off;
    }
    if (i == 0) g_off[n] = nE;
}

// bin edges by dst straight from raw edges
__global__ void bin_kernel(const void* __restrict__ ei, int nE, int n) {
    int e = blockIdx.x * blockDim.x + threadIdx.x;
    if (e >= nE) return;
    int src = load_idx(ei, e, nE, 0, n);
    int dst = load_idx(ei, e, nE, 1, n);
    int pos = atomicAdd(&g_cur[dst], 1);
    g_srcs[pos] = src;
}

// ---------------------------------------------------------------------------
// Layer-1 aggregation: one warp per dst node; mean of x rows, written
// PRE-SPLIT (bf16 hi/lo, k-pair packed) for direct GEMM staging.
// ---------------------------------------------------------------------------
__global__ void gather1_kernel(const float* __restrict__ X, int n) {
    const int gw = (blockIdx.x * blockDim.x + threadIdx.x) >> 5;
    if (gw >= n) return;
    const int lane = threadIdx.x & 31;
    const int beg = g_off[gw], end = g_off[gw + 1];

    float4 acc = make_float4(0.f, 0.f, 0.f, 0.f);
    int j = beg;
    for (; j + 4 <= end; j += 4) {
        int s0 = g_srcs[j], s1 = g_srcs[j + 1];
        int s2 = g_srcs[j + 2], s3 = g_srcs[j + 3];
        float4 v0 = ((const float4*)(X + (size_t)s0 * 128))[lane];
        float4 v1 = ((const float4*)(X + (size_t)s1 * 128))[lane];
        float4 v2 = ((const float4*)(X + (size_t)s2 * 128))[lane];
        float4 v3 = ((const float4*)(X + (size_t)s3 * 128))[lane];
        acc.x += (v0.x + v1.x) + (v2.x + v3.x);
        acc.y += (v0.y + v1.y) + (v2.y + v3.y);
        acc.z += (v0.z + v1.z) + (v2.z + v3.z);
        acc.w += (v0.w + v1.w) + (v2.w + v3.w);
    }
    for (; j < end; j++) {
        float4 v = ((const float4*)(X + (size_t)g_srcs[j] * 128))[lane];
        acc.x += v.x; acc.y += v.y; acc.z += v.z; acc.w += v.w;
    }
    float r = 1.0f / (float)max(end - beg, 1);
    acc.x *= r; acc.y *= r; acc.z *= r; acc.w *= r;
    unsigned h0, l0, h1, l1;
    split2(make_float2(acc.x, acc.y), h0, l0);
    split2(make_float2(acc.z, acc.w), h1, l1);
    size_t base = (size_t)gw * 64 + 2 * lane;
    g_aggh[base] = h0; g_aggh[base + 1] = h1;
    g_aggl[base] = l0; g_aggl[base + 1] = l1;
}

// ---------------------------------------------------------------------------
// Layer-2 aggregation: mean of g_y rows, ACCUMULATED into out
// ---------------------------------------------------------------------------
__global__ void gather2_kernel(float* __restrict__ out, int n) {
    const int gw = (blockIdx.x * blockDim.x + threadIdx.x) >> 5;
    if (gw >= n) return;
    const int lane = threadIdx.x & 31;
    const int beg = g_off[gw], end = g_off[gw + 1];

    float2 acc = make_float2(0.f, 0.f);
    int j = beg;
    for (; j + 4 <= end; j += 4) {
        int s0 = g_srcs[j], s1 = g_srcs[j + 1];
        int s2 = g_srcs[j + 2], s3 = g_srcs[j + 3];
        float2 v0 = ((const float2*)(g_y + (size_t)s0 * 64))[lane];
        float2 v1 = ((const float2*)(g_y + (size_t)s1 * 64))[lane];
        float2 v2 = ((const float2*)(g_y + (size_t)s2 * 64))[lane];
        float2 v3 = ((const float2*)(g_y + (size_t)s3 * 64))[lane];
        acc.x += (v0.x + v1.x) + (v2.x + v3.x);
        acc.y += (v0.y + v1.y) + (v2.y + v3.y);
    }
    for (; j < end; j++) {
        float2 v = ((const float2*)(g_y + (size_t)g_srcs[j] * 64))[lane];
        acc.x += v.x; acc.y += v.y;
    }
    float r = 1.0f / (float)max(end - beg, 1);
    float2* p = (float2*)(out + (size_t)gw * 64) + lane;
    float2 o = *p;
    o.x += acc.x * r;
    o.y += acc.y * r;
    *p = o;
}

// ---------------------------------------------------------------------------
// GEMM 1: h = relu([mean(x) | x] @ [W1l;W1r] + b1), written pre-split bf16.
// BM=64, BN=128, K=256. Double-buffered pipeline, KC=16 (NC=16 chunks),
// KHP=12 (conflict-free fragments, 16B-aligned rows for cp.async).
// Chunks 0-7: A = pre-split agg (cp.async).  Chunks 8-15: A = x (LDG before
// mma, split+STS after).  W always cp.async from pre-split globals.
// ---------------------------------------------------------------------------
__global__ void gemm1_kernel(const float* __restrict__ x,
                             const float* __restrict__ b1, int n) {
    constexpr int KHP = 12;
    __shared__ __align__(16) unsigned sAh[2][64 * KHP], sAl[2][64 * KHP];
    __shared__ __align__(16) unsigned sWh[2][128 * KHP], sWl[2][128 * KHP];
    const int tid = threadIdx.x;
    const int node0 = blockIdx.x * 64;
    const int warp = tid >> 5;
    const int lane = tid & 31;
    const int wm = warp & 1;
    const int wn = warp >> 1;
    const int gid = lane >> 2;
    const int tig = lane & 3;

    float4 acc[2][4];
#pragma unroll
    for (int mt = 0; mt < 2; mt++)
#pragma unroll
        for (int nt = 0; nt < 4; nt++)
            acc[mt][nt] = make_float4(0.f, 0.f, 0.f, 0.f);

    auto stage_w = [&](int c, int b) {
#pragma unroll
        for (int i = tid; i < 512; i += 256) {
            int arr = i >> 8;
            int r = (i & 255) >> 1;
            int q = i & 1;
            const unsigned* src = (arr ? g_w1l : g_w1h) + r * 128 + 8 * c + 4 * q;
            unsigned dst = smem_u32p(&(arr ? sWl : sWh)[b][r * KHP + 4 * q]);
            CPA16(dst, src, 16);
        }
    };
    auto stage_agg = [&](int c, int b) {
        int arr = tid >> 7;
        int j = tid & 127;
        int m = j >> 1, q = j & 1;
        int node = node0 + m;
        int sz = (node < n) ? 16 : 0;
        if (node >= n) node = 0;
        const unsigned* src = (arr ? g_aggl : g_aggh) + (size_t)node * 64 + 8 * c + 4 * q;
        unsigned dst = smem_u32p(&(arr ? sAl : sAh)[b][m * KHP + 4 * q]);
        CPA16(dst, src, sz);
    };

    // prologue: chunk 0
    stage_agg(0, 0);
    stage_w(0, 0);
    CPA_COMMIT(); CPA_WAIT0(); __syncthreads();

    const int xm = tid >> 2, xkq = tid & 3;     // x staging mapping

    for (int c = 0; c < 16; c++) {
        const int b = c & 1, nb = b ^ 1;
        float4 xv = make_float4(0.f, 0.f, 0.f, 0.f);
        bool nxt_x = false;
        if (c + 1 < 16) {
            if (c + 1 < 8) {
                stage_agg(c + 1, nb);
            } else {
                nxt_x = true;
                int node = node0 + xm;
                if (node < n)
                    xv = ((const float4*)(x + (size_t)node * 128 + 16 * (c + 1 - 8)))[xkq];
            }
            stage_w(c + 1, nb);
            CPA_COMMIT();
        }
        // mma on buffer b (one k16 step)
        {
            unsigned ah[2][4], al[2][4], bh[4][2], bl[4][2];
#pragma unroll
            for (int mt = 0; mt < 2; mt++) {
                int r0 = (wm * 32 + mt * 16 + gid) * KHP;
                int r1 = r0 + 8 * KHP;
                ah[mt][0] = sAh[b][r0 + tig];
                ah[mt][1] = sAh[b][r1 + tig];
                ah[mt][2] = sAh[b][r0 + tig + 4];
                ah[mt][3] = sAh[b][r1 + tig + 4];
                al[mt][0] = sAl[b][r0 + tig];
                al[mt][1] = sAl[b][r1 + tig];
                al[mt][2] = sAl[b][r0 + tig + 4];
                al[mt][3] = sAl[b][r1 + tig + 4];
            }
#pragma unroll
            for (int nt = 0; nt < 4; nt++) {
                int rn = (wn * 32 + nt * 8 + gid) * KHP;
                bh[nt][0] = sWh[b][rn + tig];
                bh[nt][1] = sWh[b][rn + tig + 4];
                bl[nt][0] = sWl[b][rn + tig];
                bl[nt][1] = sWl[b][rn + tig + 4];
            }
#pragma unroll
            for (int mt = 0; mt < 2; mt++)
#pragma unroll
                for (int nt = 0; nt < 4; nt++) {
                    mma_bf16(acc[mt][nt], ah[mt], bh[nt]);
                    mma_bf16(acc[mt][nt], ah[mt], bl[nt]);
                    mma_bf16(acc[mt][nt], al[mt], bh[nt]);
                }
        }
        if (nxt_x) {
            unsigned h0, l0, h1, l1;
            split2(make_float2(xv.x, xv.y), h0, l0);
            split2(make_float2(xv.z, xv.w), h1, l1);
            sAh[nb][xm * KHP + 2 * xkq]     = h0;
            sAh[nb][xm * KHP + 2 * xkq + 1] = h1;
            sAl[nb][xm * KHP + 2 * xkq]     = l0;
            sAl[nb][xm * KHP + 2 * xkq + 1] = l1;
        }
        if (c + 1 < 16) { CPA_WAIT0(); __syncthreads(); }
    }

    // epilogue: bias + relu, write h PRE-SPLIT (pairs (c,c+1) = k-pair packing)
#pragma unroll
    for (int mt = 0; mt < 2; mt++) {
        int r0 = node0 + wm * 32 + mt * 16 + gid;
        int r1 = r0 + 8;
#pragma unroll
        for (int nt = 0; nt < 4; nt++) {
            int c = wn * 32 + nt * 8 + tig * 2;
            float bx = b1[c], by = b1[c + 1];
            if (r0 < n) {
                float2 v = make_float2(fmaxf(acc[mt][nt].x + bx, 0.f),
                                       fmaxf(acc[mt][nt].y + by, 0.f));
                unsigned h, l; split2(v, h, l);
                g_hh[(size_t)r0 * 64 + (c >> 1)] = h;
                g_hl[(size_t)r0 * 64 + (c >> 1)] = l;
            }
            if (r1 < n) {
                float2 v = make_float2(fmaxf(acc[mt][nt].z + bx, 0.f),
                                       fmaxf(acc[mt][nt].w + by, 0.f));
                unsigned h, l; split2(v, h, l);
                g_hh[(size_t)r1 * 64 + (c >> 1)] = h;
                g_hl[(size_t)r1 * 64 + (c >> 1)] = l;
            }
        }
    }
}

// ---------------------------------------------------------------------------
// GEMM 2 combined: [y | out_partial] = h @ [W2l | W2r]  (BM=64, BN=128, K=128)
// Double-buffered pipeline, NC=8 chunks, all cp.async (A from pre-split h).
// cols 0-63 -> g_y (fp32); cols 64-127 -> out = h@W2r + b2.
// ---------------------------------------------------------------------------
__global__ void gemm2c_kernel(const float* __restrict__ b2,
                              float* __restrict__ out, int n) {
    constexpr int KHP = 12;
    __shared__ __align__(16) unsigned sAh[2][64 * KHP], sAl[2][64 * KHP];
    __shared__ __align__(16) unsigned sWh[2][128 * KHP], sWl[2][128 * KHP];
    const int tid = threadIdx.x;
    const int node0 = blockIdx.x * 64;
    const int warp = tid >> 5;
    const int lane = tid & 31;
    const int wm = warp & 1;
    const int wn = warp >> 1;
    const int gid = lane >> 2;
    const int tig = lane & 3;

    float4 acc[2][4];
#pragma unroll
    for (int mt = 0; mt < 2; mt++)
#pragma unroll
        for (int nt = 0; nt < 4; nt++)
            acc[mt][nt] = make_float4(0.f, 0.f, 0.f, 0.f);

    auto stage_w = [&](int c, int b) {
#pragma unroll
        for (int i = tid; i < 512; i += 256) {
            int arr = i >> 8;
            int r = (i & 255) >> 1;
            int q = i & 1;
            const unsigned* src = (arr ? g_w2l : g_w2h) + r * 64 + 8 * c + 4 * q;
            unsigned dst = smem_u32p(&(arr ? sWl : sWh)[b][r * KHP + 4 * q]);
            CPA16(dst, src, 16);
        }
    };
    auto stage_a = [&](int c, int b) {
        int arr = tid >> 7;
        int j = tid & 127;
        int m = j >> 1, q = j & 1;
        int node = node0 + m;
        int sz = (node < n) ? 16 : 0;
        if (node >= n) node = 0;
        const unsigned* src = (arr ? g_hl : g_hh) + (size_t)node * 64 + 8 * c + 4 * q;
        unsigned dst = smem_u32p(&(arr ? sAl : sAh)[b][m * KHP + 4 * q]);
        CPA16(dst, src, sz);
    };

    stage_a(0, 0);
    stage_w(0, 0);
    CPA_COMMIT(); CPA_WAIT0(); __syncthreads();

    for (int c = 0; c < 8; c++) {
        const int b = c & 1, nb = b ^ 1;
        if (c + 1 < 8) {
            stage_a(c + 1, nb);
            stage_w(c + 1, nb);
            CPA_COMMIT();
        }
        {
            unsigned ah[2][4], al[2][4], bh[4][2], bl[4][2];
#pragma unroll
            for (int mt = 0; mt < 2; mt++) {
                int r0 = (wm * 32 + mt * 16 + gid) * KHP;
                int r1 = r0 + 8 * KHP;
                ah[mt][0] = sAh[b][r0 + tig];
                ah[mt][1] = sAh[b][r1 + tig];
                ah[mt][2] = sAh[b][r0 + tig + 4];
                ah[mt][3] = sAh[b][r1 + tig + 4];
                al[mt][0] = sAl[b][r0 + tig];
                al[mt][1] = sAl[b][r1 + tig];
                al[mt][2] = sAl[b][r0 + tig + 4];
                al[mt][3] = sAl[b][r1 + tig + 4];
            }
#pragma unroll
            for (int nt = 0; nt < 4; nt++) {
                int rn = (wn * 32 + nt * 8 + gid) * KHP;
                bh[nt][0] = sWh[b][rn + tig];
                bh[nt][1] = sWh[b][rn + tig + 4];
                bl[nt][0] = sWl[b][rn + tig];
                bl[nt][1] = sWl[b][rn + tig + 4];
            }
#pragma unroll
            for (int mt = 0; mt < 2; mt++)
#pragma unroll
                for (int nt = 0; nt < 4; nt++) {
                    mma_bf16(acc[mt][nt], ah[mt], bh[nt]);
                    mma_bf16(acc[mt][nt], ah[mt], bl[nt]);
                    mma_bf16(acc[mt][nt], al[mt], bh[nt]);
                }
        }
        if (c + 1 < 8) { CPA_WAIT0(); __syncthreads(); }
    }

    // epilogue: cols < 64 -> g_y; cols >= 64 -> out partial (+b2)
    const bool isY = (wn < 2);
#pragma unroll
    for (int mt = 0; mt < 2; mt++) {
        int r0 = node0 + wm * 32 + mt * 16 + gid;
#pragma unroll
        for (int nt = 0; nt < 4; nt++) {
            int c = wn * 32 + nt * 8 + tig * 2;
#pragma unroll
            for (int half = 0; half < 2; half++) {
                int r = r0 + half * 8;
                if (r >= n) continue;
                float vx = half ? acc[mt][nt].z : acc[mt][nt].x;
                float vy = half ? acc[mt][nt].w : acc[mt][nt].y;
                if (isY) {
                    *(float2*)(g_y + (size_t)r * 64 + c) = make_float2(vx, vy);
                } else {
                    int co = c - 64;
                    *(float2*)(out + (size_t)r * 64 + co) =
                        make_float2(vx + b2[co], vy + b2[co + 1]);
                }
            }
        }
    }
}

// ---------------------------------------------------------------------------
// launch
// ---------------------------------------------------------------------------
extern "C" void kernel_launch(void* const* d_in, const int* in_sizes, int n_in,
                              void* d_out, int out_size) {
    const float* x   = (const float*)d_in[0];
    const void*  ei  = d_in[1];
    const float* W1l = (const float*)d_in[2];
    const float* W1r = (const float*)d_in[3];
    const float* b1  = (const float*)d_in[4];
    const float* W2l = (const float*)d_in[5];
    const float* W2r = (const float*)d_in[6];
    const float* b2  = (const float*)d_in[7];
    float* out = (float*)d_out;

    const int n  = in_sizes[0] / 128;   // 100000
    const int nE = in_sizes[1] / 2;     // 1600000
    const int nb = (n + 1023) / 1024;

    setup_kernel<<<(n + 255) / 256, 256>>>((const int*)ei, W1l, W1r, W2l, W2r, n);
    count_kernel<<<(nE + 255) / 256, 256>>>(ei, nE, n);

    scan1_kernel<<<nb, 1024>>>(n);
    scan2_kernel<<<1, 128>>>(nb);
    scan3_kernel<<<(n + 255) / 256, 256>>>(n, nE);
    bin_kernel<<<(nE + 255) / 256, 256>>>(ei, nE, n);

    // ---- Layer 1 ----
    {
        long long threads = (long long)n * 32;
        gather1_kernel<<<(unsigned)((threads + 255) / 256), 256>>>(x, n);
    }
    gemm1_kernel<<<(n + 63) / 64, 256>>>(x, b1, n);

    // ---- Layer 2 ----
    gemm2c_kernel<<<(n + 63) / 64, 256>>>(b2, out, n);
    {
        long long threads = (long long)n * 32;
        gather2_kernel<<<(unsigned)((threads + 255) / 256), 256>>>(out, n);
    }
}